// round 11
// baseline (speedup 1.0000x reference)
#include <cuda_runtime.h>
#include <math.h>

// ---------------------------------------------------------------------------
// CapsNet forward, B=32. Dominant cost: FC 102400->9216 (3.77 GB weights).
// Split-K GEMM; smem-staged k-coalesced weight tiles, XOR-swizzled [k][512];
// 512-thread blocks (16 warps/SM) so the fma pipe stays fed (R10 was
// occupancy-bound at 8 warps/SM: nothing saturated, occ 12.5%).
// Compute uses packed fp32 fma.rn.f32x2.
// ---------------------------------------------------------------------------

#define FC_M      9216
#define FC_K      102400
#define FC_SPLITK 8
#define FC_KSEG   12800     // FC_K / FC_SPLITK
#define FC_BK     32
#define FC_BM     512
#define FC_NT     400       // FC_KSEG / FC_BK

// output section offsets (concatenated tuple, fp32)
#define OFF_LOGITS 0
#define OFF_RECON  320
#define OFF_PRIM   25408
#define OFF_DIGIT  320320
#define OFF_C      325440
#define OFF_B      694080

// ---------------- device scratch (static; allocations are forbidden) -------
__device__ __align__(16) float g_xT[784 * 32];
__device__ __align__(16) float g_flatT[FC_K * 32];                 // 13.1 MB
__device__ __align__(16) float g_Cpart[FC_SPLITK * FC_M * 32];     //  9.4 MB
__device__ __align__(16) float g_capsT[FC_M * 32];
__device__ __align__(16) float g_uhatT[10 * 1152 * 16 * 32];       // 23.6 MB
__device__ __align__(16) float g_bT[10 * 1152 * 32];
__device__ __align__(16) float g_cT[10 * 1152 * 32];
__device__ __align__(16) float g_spart[10 * 36 * 16 * 32];
__device__ __align__(16) float g_v[10 * 32 * 16];
__device__ __align__(16) float g_masked[160 * 32];
__device__ __align__(16) float g_d1[512 * 32];
__device__ __align__(16) float g_d2[1024 * 32];

// ---------------- packed fp32 helpers (sm_100+) ----------------------------
__device__ __forceinline__ void fma2(unsigned long long& d,
                                     unsigned long long a,
                                     unsigned long long b) {
    asm("fma.rn.f32x2 %0, %1, %2, %0;" : "+l"(d) : "l"(a), "l"(b));
}
__device__ __forceinline__ unsigned long long dup2(float w) {
    unsigned long long r;
    asm("mov.b64 %0, {%1, %1};" : "=l"(r) : "f"(w));
    return r;
}
__device__ __forceinline__ float f4e(const float4& v, int e) {
    return e == 0 ? v.x : e == 1 ? v.y : e == 2 ? v.z : v.w;
}

// ---------------------------------------------------------------------------
// 0) x [32][784] -> xT [784][32]
// ---------------------------------------------------------------------------
__global__ void xT_kernel(const float* __restrict__ x) {
    int idx = blockIdx.x * 256 + threadIdx.x;
    if (idx < 784 * 32) {
        int b = idx / 784;
        int pix = idx - b * 784;
        g_xT[pix * 32 + b] = x[idx];
    }
}

// ---------------------------------------------------------------------------
// 1) conv 9x9 VALID + bias + relu -> flatT[k][b], k = oc*400 + oh*20 + ow
// ---------------------------------------------------------------------------
__global__ void conv_kernel(const float* __restrict__ cw,
                            const float* __restrict__ cb) {
    int idx = blockIdx.x * 256 + threadIdx.x;   // 3,276,800 threads
    int b = idx & 31;
    int k = idx >> 5;                            // 0 .. 102399
    int oc = k / 400;
    int pos = k - oc * 400;
    int oh = pos / 20;
    int ow = pos - oh * 20;
    float acc = cb[oc];
    const float* wp = cw + oc * 81;
#pragma unroll
    for (int r = 0; r < 9; ++r) {
#pragma unroll
        for (int cc = 0; cc < 9; ++cc) {
            acc = fmaf(g_xT[((oh + r) * 28 + ow + cc) * 32 + b], wp[r * 9 + cc], acc);
        }
    }
    g_flatT[(size_t)k * 32 + b] = fmaxf(acc, 0.f);
}

// ---------------------------------------------------------------------------
// tiny prep kernel (keeps fc_gemm at app-launch #4 = the ncu capture slot)
// ---------------------------------------------------------------------------
__global__ void prep_kernel() {
    int t = threadIdx.x;                         // 256
    if (t < 160) {
        for (int b = 0; b < 32; ++b) g_v[(t / 16) * 512 + b * 16 + (t & 15)] = 0.f;
    }
}

// ---------------------------------------------------------------------------
// 2) FC GEMM: Cpart[sk][m][b] = sum_{k in seg} fc_w[m][k] * flatT[k][b]
//    block 512, BM=512, BK=32, double-buffered smem for both operands.
//    Weight tile: [k][512], 16B-chunk XOR swizzle c' = c ^ ((k>>2)&7).
//    Thread owns rows 4rg..4rg+3 x batches bq*8..+7 (16 fma2 per k):
//      per k: 1 w-LDS.128 (8 distinct chunks, 4-way bcast -> 1 wf),
//             2 a-LDS.128 (4 distinct addrs, 8-way bcast -> 1 wf each).
//    16 warps/SM (4/SMSP) -> latency at chunk boundaries is covered.
// ---------------------------------------------------------------------------
#define FC_STAGE(B)                                                          \
    _Pragma("unroll")                                                        \
    for (int j = 0; j < 8; ++j) {                                            \
        _Pragma("unroll")                                                    \
        for (int e = 0; e < 4; ++e) {                                        \
            const int kk = lkg * 4 + e;                                      \
            const int ch = (((lrow >> 2) + 16 * j) ^ lkg) << 2;              \
            wsh[B][kk * FC_BM + ch + (lrow & 3)] = f4e(wreg[j], e);          \
        }                                                                    \
    }                                                                        \
    if (t < 256) ((float4*)&ash[B][0][0])[t] = areg;

__global__ void __launch_bounds__(512, 1)
fc_gemm_kernel(const float* __restrict__ fcw) {
    __shared__ __align__(16) float wsh[2][FC_BK * FC_BM];  // 128 KB, swizzled
    __shared__ __align__(16) float ash[2][FC_BK][32];      //   8 KB

    const int t = threadIdx.x;
    const int mbase = blockIdx.x * FC_BM;
    const long long kbase = (long long)blockIdx.y * FC_KSEG;

    // loader mapping: rows m = lrow + 64*j (j=0..7), k-group lkg (k=lkg*4+e)
    const int lrow = t >> 3;                 // 0..63
    const int lkg  = t & 7;                  // 0..7
    const float* wsrc = fcw + (size_t)(mbase + lrow) * FC_K + kbase + lkg * 4;
    const size_t wjstride = (size_t)64 * FC_K;
    const float4* asrc = (const float4*)(g_flatT + kbase * 32);

    // compute mapping: rows 4rg..4rg+3, batches bq*8..bq*8+7
    const int rg = t >> 2;                   // 0..127
    const int bq = t & 3;                    // 0..3

    unsigned long long acc[4][4];
#pragma unroll
    for (int r = 0; r < 4; ++r)
#pragma unroll
        for (int q = 0; q < 4; ++q) acc[r][q] = 0ull;

    float4 wreg[8];
    float4 areg;

    // ---- prologue: load + stage tile 0 ----
#pragma unroll
    for (int j = 0; j < 8; ++j)
        wreg[j] = *(const float4*)(wsrc + j * wjstride);
    if (t < 256) areg = asrc[t];
    FC_STAGE(0)
    __syncthreads();

#pragma unroll 1
    for (int c = 0; c < FC_NT; ++c) {
        const int buf = c & 1;
        const bool more = (c + 1) < FC_NT;
        if (more) {
            const float* wp = wsrc + (size_t)(c + 1) * FC_BK;
#pragma unroll
            for (int j = 0; j < 8; ++j)
                wreg[j] = *(const float4*)(wp + j * wjstride);
            if (t < 256) areg = asrc[(size_t)(c + 1) * 256 + t];
        }

        // ---- compute 32 k on buffer `buf` ----
#pragma unroll
        for (int k = 0; k < FC_BK; ++k) {
            const int s = (k >> 2) & 7;
            const float4 wa = *(const float4*)
                &wsh[buf][k * FC_BM + ((rg ^ s) << 2)];
            const ulonglong2 fa = *(const ulonglong2*)&ash[buf][k][bq * 8];
            const ulonglong2 fb = *(const ulonglong2*)&ash[buf][k][bq * 8 + 4];
            unsigned long long f[4];
            f[0] = fa.x; f[1] = fa.y; f[2] = fb.x; f[3] = fb.y;
            unsigned long long w[4];
            w[0] = dup2(wa.x); w[1] = dup2(wa.y);
            w[2] = dup2(wa.z); w[3] = dup2(wa.w);
#pragma unroll
            for (int r = 0; r < 4; ++r)
#pragma unroll
                for (int q = 0; q < 4; ++q)
                    fma2(acc[r][q], w[r], f[q]);
        }

        if (more) {
            const int nb = buf ^ 1;
            FC_STAGE(nb)
        }
        __syncthreads();
    }

    // ---- epilogue: rows mbase + 4rg + r, batches bq*8..+7 ----
#pragma unroll
    for (int r = 0; r < 4; ++r) {
        float* dst = g_Cpart +
            ((size_t)blockIdx.y * FC_M + mbase + 4 * rg + r) * 32 + bq * 8;
        float2 p0 = *(float2*)&acc[r][0];
        float2 p1 = *(float2*)&acc[r][1];
        float2 p2 = *(float2*)&acc[r][2];
        float2 p3 = *(float2*)&acc[r][3];
        *(float4*)(dst)     = make_float4(p0.x, p0.y, p1.x, p1.y);
        *(float4*)(dst + 4) = make_float4(p2.x, p2.y, p3.x, p3.y);
    }
}

// ---------------------------------------------------------------------------
// 3) reduce split-K + bias + squash -> primary caps output + capsT scratch
// ---------------------------------------------------------------------------
__global__ void caps_kernel(const float* __restrict__ fcb,
                            float* __restrict__ out) {
    int idx = blockIdx.x * 256 + threadIdx.x;   // 36864
    int b = idx & 31;
    int cap = idx >> 5;
    float pc[8];
    float n2 = 0.f;
#pragma unroll
    for (int d = 0; d < 8; ++d) {
        int m = cap * 8 + d;
        float v = fcb[m];
#pragma unroll
        for (int s = 0; s < FC_SPLITK; ++s)
            v += g_Cpart[((size_t)s * FC_M + m) * 32 + b];
        pc[d] = v;
        n2 += v * v;
    }
    float scale = n2 / (1.f + n2);
    float inv = 1.f / sqrtf(n2);
#pragma unroll
    for (int d = 0; d < 8; ++d) {
        float o = scale * (pc[d] * inv + 1e-8f);
        out[OFF_PRIM + (size_t)b * 9216 + cap * 8 + d] = o;
        g_capsT[(cap * 8 + d) * 32 + b] = o;
    }
}

// ---------------------------------------------------------------------------
// 4) u_hat[b,n,p,d] = sum_i W[0,n,p,d,i] * caps[b,p,i] -> g_uhatT[n][p][d][b]
// ---------------------------------------------------------------------------
__global__ void uhat_kernel(const float* __restrict__ W) {
    int idx = blockIdx.x * 256 + threadIdx.x;   // 368640
    int b = idx & 31;
    int r = idx >> 5;                            // n*1152 + p
    int p = r % 1152;
    float caps[8];
#pragma unroll
    for (int i = 0; i < 8; ++i) caps[i] = g_capsT[(p * 8 + i) * 32 + b];
    const float* Wp = W + (size_t)r * 128;       // warp-uniform broadcast
    float* up = g_uhatT + (size_t)r * 512 + b;
#pragma unroll
    for (int d = 0; d < 16; ++d) {
        float a = 0.f;
#pragma unroll
        for (int i = 0; i < 8; ++i) a = fmaf(Wp[d * 8 + i], caps[i], a);
        up[d * 32] = a;
    }
}

// ---------------------------------------------------------------------------
// 5a) partial s sums over p-chunks of 32: spart[n][ch][d][b]
// ---------------------------------------------------------------------------
__global__ void rout_sv_kernel(int uniformC) {
    int n = blockIdx.x / 36;
    int ch = blockIdx.x - n * 36;
    int t = threadIdx.x;                         // 512 = 16 d * 32 b
    int b = t & 31;
    int d = t >> 5;
    int rbase = n * 1152 + ch * 32;
    float a = 0.f;
#pragma unroll 8
    for (int pp = 0; pp < 32; ++pp) {
        size_t r = rbase + pp;
        float c = uniformC ? 0.1f : g_cT[r * 32 + b];
        a = fmaf(c, g_uhatT[(r * 16 + d) * 32 + b], a);
    }
    g_spart[(((size_t)n * 36 + ch) * 16 + d) * 32 + b] = a;
}

// 5b) reduce partials + squash -> v (and digit caps output when final)
__global__ void rout_squash_kernel(int final_, float* __restrict__ out) {
    int t = threadIdx.x;                         // 320
    int b = t & 31;
    int n = t >> 5;
    float s[16];
    float n2 = 0.f;
#pragma unroll
    for (int d = 0; d < 16; ++d) {
        float a = 0.f;
        for (int ch = 0; ch < 36; ++ch)
            a += g_spart[(((size_t)n * 36 + ch) * 16 + d) * 32 + b];
        s[d] = a;
        n2 += a * a;
    }
    float scale = n2 / (1.f + n2);
    float inv = 1.f / sqrtf(n2);
#pragma unroll
    for (int d = 0; d < 16; ++d) {
        float v = scale * (s[d] * inv + 1e-8f);
        g_v[(n * 32 + b) * 16 + d] = v;
        if (final_) out[OFF_DIGIT + (size_t)b * 160 + n * 16 + d] = v;
    }
}

// 5c) b += sum_d u_hat * v   (first iteration: b = uv, since b starts at 0)
__global__ void rout_update_kernel(int first) {
    int idx = blockIdx.x * 256 + threadIdx.x;   // 368640
    int b = idx & 31;
    int r = idx >> 5;
    int n = r / 1152;
    const float* up = g_uhatT + (size_t)r * 512 + b;
    const float* vp = g_v + ((size_t)n * 32 + b) * 16;
    float a = 0.f;
#pragma unroll
    for (int d = 0; d < 16; ++d) a = fmaf(up[d * 32], vp[d], a);
    size_t o = (size_t)r * 32 + b;
    g_bT[o] = (first ? 0.f : g_bT[o]) + a;
}

// 5d) c = softmax over n of b; optionally emit final c and b to output
__global__ void softmax_kernel(int write_out, float* __restrict__ out) {
    int idx = blockIdx.x * 256 + threadIdx.x;   // 36864
    int b = idx & 31;
    int p = idx >> 5;
    float bv[10];
    float m = -1e30f;
#pragma unroll
    for (int n = 0; n < 10; ++n) {
        bv[n] = g_bT[((size_t)n * 1152 + p) * 32 + b];
        m = fmaxf(m, bv[n]);
    }
    float e[10];
    float sum = 0.f;
#pragma unroll
    for (int n = 0; n < 10; ++n) {
        e[n] = expf(bv[n] - m);
        sum += e[n];
    }
    float invs = 1.f / sum;
#pragma unroll
    for (int n = 0; n < 10; ++n) {
        float c = e[n] * invs;
        g_cT[((size_t)n * 1152 + p) * 32 + b] = c;
        if (write_out) {
            out[OFF_C + ((size_t)b * 10 + n) * 1152 + p] = c;
            out[OFF_B + ((size_t)b * 10 + n) * 1152 + p] = bv[n];
        }
    }
}

// ---------------------------------------------------------------------------
// 6) logits = ||digit||, argmax (first max), masked -> g_masked[i][b]
// ---------------------------------------------------------------------------
__global__ void logits_kernel(float* __restrict__ out) {
    int b = threadIdx.x;                         // 32
    float dg[160];
    for (int i = 0; i < 160; ++i) dg[i] = out[OFF_DIGIT + (size_t)b * 160 + i];
    float best = -1.f;
    int am = 0;
    for (int n = 0; n < 10; ++n) {
        float n2 = 0.f;
        for (int d = 0; d < 16; ++d) {
            float v = dg[n * 16 + d];
            n2 += v * v;
        }
        float lg = sqrtf(n2);
        out[OFF_LOGITS + b * 10 + n] = lg;
        if (lg > best) { best = lg; am = n; }
    }
    for (int n = 0; n < 10; ++n)
        for (int d = 0; d < 16; ++d)
            g_masked[(n * 16 + d) * 32 + b] = (n == am) ? dg[n * 16 + d] : 0.f;
}

// ---------------------------------------------------------------------------
// 7) decoder MLP
// ---------------------------------------------------------------------------
__global__ void dec1_kernel(const float* __restrict__ Wt,
                            const float* __restrict__ bias) {
    int idx = blockIdx.x * 256 + threadIdx.x;   // 512*32
    int b = idx & 31, o = idx >> 5;
    const float* w = Wt + (size_t)o * 160;
    float a0 = 0.f, a1 = 0.f, a2 = 0.f, a3 = 0.f;
#pragma unroll 4
    for (int i = 0; i < 160; i += 4) {
        a0 = fmaf(w[i],     g_masked[(i)     * 32 + b], a0);
        a1 = fmaf(w[i + 1], g_masked[(i + 1) * 32 + b], a1);
        a2 = fmaf(w[i + 2], g_masked[(i + 2) * 32 + b], a2);
        a3 = fmaf(w[i + 3], g_masked[(i + 3) * 32 + b], a3);
    }
    g_d1[o * 32 + b] = fmaxf(bias[o] + ((a0 + a1) + (a2 + a3)), 0.f);
}

__global__ void dec2_kernel(const float* __restrict__ Wt,
                            const float* __restrict__ bias) {
    int idx = blockIdx.x * 256 + threadIdx.x;   // 1024*32
    int b = idx & 31, o = idx >> 5;
    const float* w = Wt + (size_t)o * 512;
    float a0 = 0.f, a1 = 0.f, a2 = 0.f, a3 = 0.f;
#pragma unroll 4
    for (int i = 0; i < 512; i += 4) {
        a0 = fmaf(w[i],     g_d1[(i)     * 32 + b], a0);
        a1 = fmaf(w[i + 1], g_d1[(i + 1) * 32 + b], a1);
        a2 = fmaf(w[i + 2], g_d1[(i + 2) * 32 + b], a2);
        a3 = fmaf(w[i + 3], g_d1[(i + 3) * 32 + b], a3);
    }
    g_d2[o * 32 + b] = fmaxf(bias[o] + ((a0 + a1) + (a2 + a3)), 0.f);
}

__global__ void dec3_kernel(const float* __restrict__ Wt,
                            const float* __restrict__ bias,
                            float* __restrict__ out) {
    int idx = blockIdx.x * 256 + threadIdx.x;   // 784*32
    int b = idx & 31, o = idx >> 5;
    const float* w = Wt + (size_t)o * 1024;
    float a0 = 0.f, a1 = 0.f, a2 = 0.f, a3 = 0.f;
#pragma unroll 4
    for (int i = 0; i < 1024; i += 4) {
        a0 = fmaf(w[i],     g_d2[(i)     * 32 + b], a0);
        a1 = fmaf(w[i + 1], g_d2[(i + 1) * 32 + b], a1);
        a2 = fmaf(w[i + 2], g_d2[(i + 2) * 32 + b], a2);
        a3 = fmaf(w[i + 3], g_d2[(i + 3) * 32 + b], a3);
    }
    float x = bias[o] + ((a0 + a1) + (a2 + a3));
    out[OFF_RECON + (size_t)b * 784 + o] = 1.f / (1.f + expf(-x));
}

// ---------------------------------------------------------------------------
// Resolve inputs by (unique) element count — order-independent binding.
// ---------------------------------------------------------------------------
static const float* by_size(void* const* d_in, const int* s, int n, int want) {
    for (int i = 0; i < n; ++i)
        if (s[i] == want) return (const float*)d_in[i];
    return nullptr;
}

extern "C" void kernel_launch(void* const* d_in, const int* in_sizes, int n_in,
                              void* d_out, int out_size) {
    const float* x   = by_size(d_in, in_sizes, n_in, 32 * 784);        // 25088
    const float* cw  = by_size(d_in, in_sizes, n_in, 256 * 81);        // 20736
    const float* cb  = by_size(d_in, in_sizes, n_in, 256);
    const float* fcw = by_size(d_in, in_sizes, n_in, 943718400);       // 9216*102400
    const float* fcb = by_size(d_in, in_sizes, n_in, 9216);
    const float* W   = by_size(d_in, in_sizes, n_in, 1474560);         // 10*1152*16*8
    const float* d1w = by_size(d_in, in_sizes, n_in, 512 * 160);       // 81920
    const float* d1b = by_size(d_in, in_sizes, n_in, 512);
    const float* d2w = by_size(d_in, in_sizes, n_in, 1024 * 512);      // 524288
    const float* d2b = by_size(d_in, in_sizes, n_in, 1024);
    const float* d3w = by_size(d_in, in_sizes, n_in, 784 * 1024);      // 802816
    const float* d3b = by_size(d_in, in_sizes, n_in, 784);
    float* out = (float*)d_out;

    xT_kernel<<<98, 256>>>(x);                           // launch 1
    conv_kernel<<<12800, 256>>>(cw, cb);                 // launch 2
    prep_kernel<<<1, 256>>>();                           // launch 3
    fc_gemm_kernel<<<dim3(18, 8), 512>>>(fcw);           // launch 4 <- ncu slot
    caps_kernel<<<144, 256>>>(fcb, out);
    uhat_kernel<<<1440, 256>>>(W);

    // routing iteration 0 (c = softmax(0) = 0.1 uniform)
    rout_sv_kernel<<<360, 512>>>(1);
    rout_squash_kernel<<<1, 320>>>(0, out);
    rout_update_kernel<<<1440, 256>>>(1);
    // routing iteration 1
    softmax_kernel<<<144, 256>>>(0, out);
    rout_sv_kernel<<<360, 512>>>(0);
    rout_squash_kernel<<<1, 320>>>(0, out);
    rout_update_kernel<<<1440, 256>>>(0);
    // final pass (emit c, b, digit caps)
    softmax_kernel<<<144, 256>>>(1, out);
    rout_sv_kernel<<<360, 512>>>(0);
    rout_squash_kernel<<<1, 320>>>(1, out);

    logits_kernel<<<1, 32>>>(out);
    dec1_kernel<<<64, 256>>>(d1w, d1b);
    dec2_kernel<<<128, 256>>>(d2w, d2b);
    dec3_kernel<<<98, 256>>>(d3w, d3b, out);
}

// round 13
// speedup vs baseline: 1.0683x; 1.0683x over previous
#include <cuda_runtime.h>
#include <cuda_bf16.h>
#include <math.h>
#include <stdint.h>

// ---------------------------------------------------------------------------
// CapsNet forward, B=32. Dominant cost: FC 102400->9216 (3.77 GB weights).
// R13: FC via arch-generic mma.sync bf16 (m16n8k16) with hi/lo split
// (tcgen05 PTX is rejected: harness compiles at target sm_103, not sm_103a).
// DRAM-bound design: weights stream once; acts live in L2.
// ---------------------------------------------------------------------------

#define FC_M      9216
#define FC_K      102400
#define FC_SPLITK 8
#define FC_KSEG   12800     // FC_K / FC_SPLITK
#define FC_NCH    800       // FC_KSEG / 16
#define AST       12        // smem words per bf16 row (48B: 16 bf16 + pad)

// output section offsets (concatenated tuple, fp32)
#define OFF_LOGITS 0
#define OFF_RECON  320
#define OFF_PRIM   25408
#define OFF_DIGIT  320320
#define OFF_C      325440
#define OFF_B      694080

// ---------------- device scratch (static; allocations are forbidden) -------
__device__ __align__(16) float g_xT[784 * 32];
__device__ __align__(16) float g_flatT[FC_K * 32];                 // 13.1 MB
__device__ __align__(16) __nv_bfloat16 g_actH[32 * FC_K];          //  6.6 MB
__device__ __align__(16) __nv_bfloat16 g_actL[32 * FC_K];          //  6.6 MB
__device__ __align__(16) float g_Cpart[FC_SPLITK * FC_M * 32];     //  9.4 MB
__device__ __align__(16) float g_capsT[FC_M * 32];
__device__ __align__(16) float g_uhatT[10 * 1152 * 16 * 32];       // 23.6 MB
__device__ __align__(16) float g_bT[10 * 1152 * 32];
__device__ __align__(16) float g_cT[10 * 1152 * 32];
__device__ __align__(16) float g_spart[10 * 36 * 16 * 32];
__device__ __align__(16) float g_v[10 * 32 * 16];
__device__ __align__(16) float g_masked[160 * 32];
__device__ __align__(16) float g_d1[512 * 32];
__device__ __align__(16) float g_d2[1024 * 32];

// ---------------- helpers ---------------------------------------------------
__device__ __forceinline__ void split_bf2(float a, float b,
                                          uint32_t& hi, uint32_t& lo) {
    __nv_bfloat16 ha = __float2bfloat16_rn(a);
    __nv_bfloat16 hb = __float2bfloat16_rn(b);
    __nv_bfloat16 la = __float2bfloat16_rn(a - __bfloat162float(ha));
    __nv_bfloat16 lb = __float2bfloat16_rn(b - __bfloat162float(hb));
    hi = (uint32_t)__bfloat16_as_ushort(ha) |
         ((uint32_t)__bfloat16_as_ushort(hb) << 16);
    lo = (uint32_t)__bfloat16_as_ushort(la) |
         ((uint32_t)__bfloat16_as_ushort(lb) << 16);
}
// mma.sync m16n8k16 row.col f32.bf16.bf16.f32 (arch-generic, sm_80+)
__device__ __forceinline__ void mma16816(float* c,
                                         uint32_t a0, uint32_t a1,
                                         uint32_t a2, uint32_t a3,
                                         uint32_t b0, uint32_t b1) {
    asm volatile(
        "mma.sync.aligned.m16n8k16.row.col.f32.bf16.bf16.f32 "
        "{%0,%1,%2,%3}, {%4,%5,%6,%7}, {%8,%9}, {%0,%1,%2,%3};"
        : "+f"(c[0]), "+f"(c[1]), "+f"(c[2]), "+f"(c[3])
        : "r"(a0), "r"(a1), "r"(a2), "r"(a3), "r"(b0), "r"(b1));
}

// ---------------------------------------------------------------------------
// 0) x [32][784] -> xT [784][32]
// ---------------------------------------------------------------------------
__global__ void xT_kernel(const float* __restrict__ x) {
    int idx = blockIdx.x * 256 + threadIdx.x;
    if (idx < 784 * 32) {
        int b = idx / 784;
        int pix = idx - b * 784;
        g_xT[pix * 32 + b] = x[idx];
    }
}

// ---------------------------------------------------------------------------
// 1) conv 9x9 VALID + bias + relu -> flatT[k][b]
// ---------------------------------------------------------------------------
__global__ void conv_kernel(const float* __restrict__ cw,
                            const float* __restrict__ cb) {
    int idx = blockIdx.x * 256 + threadIdx.x;
    int b = idx & 31;
    int k = idx >> 5;
    int oc = k / 400;
    int pos = k - oc * 400;
    int oh = pos / 20;
    int ow = pos - oh * 20;
    float acc = cb[oc];
    const float* wp = cw + oc * 81;
#pragma unroll
    for (int r = 0; r < 9; ++r) {
#pragma unroll
        for (int cc = 0; cc < 9; ++cc) {
            acc = fmaf(g_xT[((oh + r) * 28 + ow + cc) * 32 + b], wp[r * 9 + cc], acc);
        }
    }
    g_flatT[(size_t)k * 32 + b] = fmaxf(acc, 0.f);
}

// ---------------------------------------------------------------------------
// 1b) act hi/lo bf16 split: flatT[k][b] -> actH/actL[b][k]
// ---------------------------------------------------------------------------
__global__ void actcvt_kernel() {
    int idx = blockIdx.x * 256 + threadIdx.x;    // 3,276,800
    int b = idx / FC_K;
    int k = idx - b * FC_K;
    float f = g_flatT[(size_t)k * 32 + b];
    __nv_bfloat16 h = __float2bfloat16_rn(f);
    g_actH[(size_t)b * FC_K + k] = h;
    g_actL[(size_t)b * FC_K + k] = __float2bfloat16_rn(f - __bfloat162float(h));
}

// ---------------------------------------------------------------------------
// 2) FC via mma.sync bf16 hi/lo: Cpart[sk][m][b] = sum_k W[m][k]*act[b][k]
//    Block 256 thr = 8 warps, BM=128 (m16/warp), N=32 (4 n8 tiles), BK=16.
//    Per chunk: LDG fp32 weights (k-coalesced), split->bf16 hi/lo in 48B-
//    stride smem rows (frag LDS conflict-free), 12 MMA/warp (hh, hl, lh).
// ---------------------------------------------------------------------------
__global__ void __launch_bounds__(256, 2)
fc_hmma_kernel(const float* __restrict__ fcw) {
    __shared__ __align__(16) uint32_t aH[2][128 * AST];   // 12 KB
    __shared__ __align__(16) uint32_t aL[2][128 * AST];   // 12 KB
    __shared__ __align__(16) uint32_t bHs[2][32 * AST];   //  3 KB
    __shared__ __align__(16) uint32_t bLs[2][32 * AST];   //  3 KB

    const int t = threadIdx.x;
    const int mbase = blockIdx.x * 128;
    const long long kbase = (long long)blockIdx.y * FC_KSEG;

    // A loader: rows lr, lr+64; float4 col group lc (floats lc*4..lc*4+3)
    const int lr = t >> 2;                   // 0..63
    const int lc = t & 3;                    // 0..3
    const float* wp0 = fcw + (size_t)(mbase + lr) * FC_K + kbase + lc * 4;
    const float* wp1 = wp0 + (size_t)64 * FC_K;
    // B loader: threads 0..127 (t<64 -> hi, else lo); n=(t&63)>>1, half=t&1
    const int bn = (t & 63) >> 1;
    const int bh2 = t & 1;
    const __nv_bfloat16* bsrc =
        (t < 64 ? g_actH : g_actL) + (size_t)bn * FC_K + kbase + bh2 * 8;

    // compute mapping
    const int w = t >> 5;                    // warp: rows w*16..w*16+15
    const int lane = t & 31;
    const int gr = lane >> 2;                // 0..7
    const int gc = lane & 3;                 // 0..3

    float acc[4][4];
#pragma unroll
    for (int j = 0; j < 4; ++j)
#pragma unroll
        for (int q = 0; q < 4; ++q) acc[j][q] = 0.f;

    float4 a0, a1;
    uint4 bv;

    // ---- prologue: chunk 0 load + stage ----
    a0 = *(const float4*)(wp0);
    a1 = *(const float4*)(wp1);
    if (t < 128) bv = *(const uint4*)bsrc;
    {
        uint32_t h0, l0, h1, l1;
        split_bf2(a0.x, a0.y, h0, l0);
        split_bf2(a0.z, a0.w, h1, l1);
        int wd = lr * AST + lc * 2;
        *(uint2*)&aH[0][wd] = make_uint2(h0, h1);
        *(uint2*)&aL[0][wd] = make_uint2(l0, l1);
        split_bf2(a1.x, a1.y, h0, l0);
        split_bf2(a1.z, a1.w, h1, l1);
        wd = (lr + 64) * AST + lc * 2;
        *(uint2*)&aH[0][wd] = make_uint2(h0, h1);
        *(uint2*)&aL[0][wd] = make_uint2(l0, l1);
        if (t < 128) {
            uint32_t* bt = (t < 64) ? bHs[0] : bLs[0];
            *(uint4*)&bt[bn * AST + bh2 * 4] = bv;
        }
    }
    __syncthreads();

#pragma unroll 1
    for (int c = 0; c < FC_NCH; ++c) {
        const int buf = c & 1;
        const bool more = (c + 1) < FC_NCH;
        if (more) {
            a0 = *(const float4*)(wp0 + (size_t)(c + 1) * 16);
            a1 = *(const float4*)(wp1 + (size_t)(c + 1) * 16);
            if (t < 128) bv = *(const uint4*)(bsrc + (size_t)(c + 1) * 16);
        }

        // ---- compute chunk c ----
        {
            const int ab = w * 16 + gr;
            const uint32_t ah0 = aH[buf][ab * AST + gc];
            const uint32_t ah1 = aH[buf][(ab + 8) * AST + gc];
            const uint32_t ah2 = aH[buf][ab * AST + 4 + gc];
            const uint32_t ah3 = aH[buf][(ab + 8) * AST + 4 + gc];
            const uint32_t al0 = aL[buf][ab * AST + gc];
            const uint32_t al1 = aL[buf][(ab + 8) * AST + gc];
            const uint32_t al2 = aL[buf][ab * AST + 4 + gc];
            const uint32_t al3 = aL[buf][(ab + 8) * AST + 4 + gc];
#pragma unroll
            for (int j = 0; j < 4; ++j) {
                const int nb = (j * 8 + gr) * AST + gc;
                const uint32_t bh0 = bHs[buf][nb];
                const uint32_t bh1 = bHs[buf][nb + 4];
                const uint32_t bl0 = bLs[buf][nb];
                const uint32_t bl1 = bLs[buf][nb + 4];
                mma16816(acc[j], ah0, ah1, ah2, ah3, bh0, bh1);   // hi*hi
                mma16816(acc[j], ah0, ah1, ah2, ah3, bl0, bl1);   // hi*lo
                mma16816(acc[j], al0, al1, al2, al3, bh0, bh1);   // lo*hi
            }
        }

        // ---- stage chunk c+1 into buf^1 ----
        if (more) {
            const int nbuf = buf ^ 1;
            uint32_t h0, l0, h1, l1;
            split_bf2(a0.x, a0.y, h0, l0);
            split_bf2(a0.z, a0.w, h1, l1);
            int wd = lr * AST + lc * 2;
            *(uint2*)&aH[nbuf][wd] = make_uint2(h0, h1);
            *(uint2*)&aL[nbuf][wd] = make_uint2(l0, l1);
            split_bf2(a1.x, a1.y, h0, l0);
            split_bf2(a1.z, a1.w, h1, l1);
            wd = (lr + 64) * AST + lc * 2;
            *(uint2*)&aH[nbuf][wd] = make_uint2(h0, h1);
            *(uint2*)&aL[nbuf][wd] = make_uint2(l0, l1);
            if (t < 128) {
                uint32_t* bt = (t < 64) ? bHs[nbuf] : bLs[nbuf];
                *(uint4*)&bt[bn * AST + bh2 * 4] = bv;
            }
        }
        __syncthreads();
    }

    // ---- epilogue: C[m][n] fragments -> g_Cpart ----
    const int m0 = mbase + w * 16 + gr;
#pragma unroll
    for (int j = 0; j < 4; ++j) {
        const int n0 = j * 8 + gc * 2;
        float* d0 = g_Cpart + ((size_t)blockIdx.y * FC_M + m0) * 32 + n0;
        float* d1 = d0 + (size_t)8 * 32;
        *(float2*)d0 = make_float2(acc[j][0], acc[j][1]);
        *(float2*)d1 = make_float2(acc[j][2], acc[j][3]);
    }
}

// ---------------------------------------------------------------------------
// 3) reduce split-K + bias + squash -> primary caps output + capsT scratch
// ---------------------------------------------------------------------------
__global__ void caps_kernel(const float* __restrict__ fcb,
                            float* __restrict__ out) {
    int idx = blockIdx.x * 256 + threadIdx.x;   // 36864
    int b = idx & 31;
    int cap = idx >> 5;
    float pc[8];
    float n2 = 0.f;
#pragma unroll
    for (int d = 0; d < 8; ++d) {
        int m = cap * 8 + d;
        float v = fcb[m];
#pragma unroll
        for (int s = 0; s < FC_SPLITK; ++s)
            v += g_Cpart[((size_t)s * FC_M + m) * 32 + b];
        pc[d] = v;
        n2 += v * v;
    }
    float scale = n2 / (1.f + n2);
    float inv = 1.f / sqrtf(n2);
#pragma unroll
    for (int d = 0; d < 8; ++d) {
        float o = scale * (pc[d] * inv + 1e-8f);
        out[OFF_PRIM + (size_t)b * 9216 + cap * 8 + d] = o;
        g_capsT[(cap * 8 + d) * 32 + b] = o;
    }
}

// ---------------------------------------------------------------------------
// 4) u_hat[b,n,p,d] = sum_i W[0,n,p,d,i] * caps[b,p,i] -> g_uhatT[n][p][d][b]
// ---------------------------------------------------------------------------
__global__ void uhat_kernel(const float* __restrict__ W) {
    int idx = blockIdx.x * 256 + threadIdx.x;   // 368640
    int b = idx & 31;
    int r = idx >> 5;                            // n*1152 + p
    int p = r % 1152;
    float caps[8];
#pragma unroll
    for (int i = 0; i < 8; ++i) caps[i] = g_capsT[(p * 8 + i) * 32 + b];
    const float* Wp = W + (size_t)r * 128;       // warp-uniform broadcast
    float* up = g_uhatT + (size_t)r * 512 + b;
#pragma unroll
    for (int d = 0; d < 16; ++d) {
        float a = 0.f;
#pragma unroll
        for (int i = 0; i < 8; ++i) a = fmaf(Wp[d * 8 + i], caps[i], a);
        up[d * 32] = a;
    }
}

// ---------------------------------------------------------------------------
// 5a) partial s sums over p-chunks of 32: spart[n][ch][d][b]
// ---------------------------------------------------------------------------
__global__ void rout_sv_kernel(int uniformC) {
    int n = blockIdx.x / 36;
    int ch = blockIdx.x - n * 36;
    int t = threadIdx.x;                         // 512 = 16 d * 32 b
    int b = t & 31;
    int d = t >> 5;
    int rbase = n * 1152 + ch * 32;
    float a = 0.f;
#pragma unroll 8
    for (int pp = 0; pp < 32; ++pp) {
        size_t r = rbase + pp;
        float c = uniformC ? 0.1f : g_cT[r * 32 + b];
        a = fmaf(c, g_uhatT[(r * 16 + d) * 32 + b], a);
    }
    g_spart[(((size_t)n * 36 + ch) * 16 + d) * 32 + b] = a;
}

// 5b) reduce partials + squash -> v (and digit caps output when final)
__global__ void rout_squash_kernel(int final_, float* __restrict__ out) {
    int t = threadIdx.x;                         // 320
    int b = t & 31;
    int n = t >> 5;
    float s[16];
    float n2 = 0.f;
#pragma unroll
    for (int d = 0; d < 16; ++d) {
        float a = 0.f;
        for (int ch = 0; ch < 36; ++ch)
            a += g_spart[(((size_t)n * 36 + ch) * 16 + d) * 32 + b];
        s[d] = a;
        n2 += a * a;
    }
    float scale = n2 / (1.f + n2);
    float inv = 1.f / sqrtf(n2);
#pragma unroll
    for (int d = 0; d < 16; ++d) {
        float v = scale * (s[d] * inv + 1e-8f);
        g_v[(n * 32 + b) * 16 + d] = v;
        if (final_) out[OFF_DIGIT + (size_t)b * 160 + n * 16 + d] = v;
    }
}

// 5c) b += sum_d u_hat * v   (first iteration: b = uv, since b starts at 0)
__global__ void rout_update_kernel(int first) {
    int idx = blockIdx.x * 256 + threadIdx.x;   // 368640
    int b = idx & 31;
    int r = idx >> 5;
    int n = r / 1152;
    const float* up = g_uhatT + (size_t)r * 512 + b;
    const float* vp = g_v + ((size_t)n * 32 + b) * 16;
    float a = 0.f;
#pragma unroll
    for (int d = 0; d < 16; ++d) a = fmaf(up[d * 32], vp[d], a);
    size_t o = (size_t)r * 32 + b;
    g_bT[o] = (first ? 0.f : g_bT[o]) + a;
}

// 5d) c = softmax over n of b; optionally emit final c and b to output
__global__ void softmax_kernel(int write_out, float* __restrict__ out) {
    int idx = blockIdx.x * 256 + threadIdx.x;   // 36864
    int b = idx & 31;
    int p = idx >> 5;
    float bv[10];
    float m = -1e30f;
#pragma unroll
    for (int n = 0; n < 10; ++n) {
        bv[n] = g_bT[((size_t)n * 1152 + p) * 32 + b];
        m = fmaxf(m, bv[n]);
    }
    float e[10];
    float sum = 0.f;
#pragma unroll
    for (int n = 0; n < 10; ++n) {
        e[n] = expf(bv[n] - m);
        sum += e[n];
    }
    float invs = 1.f / sum;
#pragma unroll
    for (int n = 0; n < 10; ++n) {
        float c = e[n] * invs;
        g_cT[((size_t)n * 1152 + p) * 32 + b] = c;
        if (write_out) {
            out[OFF_C + ((size_t)b * 10 + n) * 1152 + p] = c;
            out[OFF_B + ((size_t)b * 10 + n) * 1152 + p] = bv[n];
        }
    }
}

// ---------------------------------------------------------------------------
// 6) logits = ||digit||, argmax (first max), masked -> g_masked[i][b]
// ---------------------------------------------------------------------------
__global__ void logits_kernel(float* __restrict__ out) {
    int b = threadIdx.x;                         // 32
    float dg[160];
    for (int i = 0; i < 160; ++i) dg[i] = out[OFF_DIGIT + (size_t)b * 160 + i];
    float best = -1.f;
    int am = 0;
    for (int n = 0; n < 10; ++n) {
        float n2 = 0.f;
        for (int d = 0; d < 16; ++d) {
            float v = dg[n * 16 + d];
            n2 += v * v;
        }
        float lg = sqrtf(n2);
        out[OFF_LOGITS + b * 10 + n] = lg;
        if (lg > best) { best = lg; am = n; }
    }
    for (int n = 0; n < 10; ++n)
        for (int d = 0; d < 16; ++d)
            g_masked[(n * 16 + d) * 32 + b] = (n == am) ? dg[n * 16 + d] : 0.f;
}

// ---------------------------------------------------------------------------
// 7) decoder MLP
// ---------------------------------------------------------------------------
__global__ void dec1_kernel(const float* __restrict__ Wt,
                            const float* __restrict__ bias) {
    int idx = blockIdx.x * 256 + threadIdx.x;   // 512*32
    int b = idx & 31, o = idx >> 5;
    const float* w = Wt + (size_t)o * 160;
    float a0 = 0.f, a1 = 0.f, a2 = 0.f, a3 = 0.f;
#pragma unroll 4
    for (int i = 0; i < 160; i += 4) {
        a0 = fmaf(w[i],     g_masked[(i)     * 32 + b], a0);
        a1 = fmaf(w[i + 1], g_masked[(i + 1) * 32 + b], a1);
        a2 = fmaf(w[i + 2], g_masked[(i + 2) * 32 + b], a2);
        a3 = fmaf(w[i + 3], g_masked[(i + 3) * 32 + b], a3);
    }
    g_d1[o * 32 + b] = fmaxf(bias[o] + ((a0 + a1) + (a2 + a3)), 0.f);
}

__global__ void dec2_kernel(const float* __restrict__ Wt,
                            const float* __restrict__ bias) {
    int idx = blockIdx.x * 256 + threadIdx.x;   // 1024*32
    int b = idx & 31, o = idx >> 5;
    const float* w = Wt + (size_t)o * 512;
    float a0 = 0.f, a1 = 0.f, a2 = 0.f, a3 = 0.f;
#pragma unroll 4
    for (int i = 0; i < 512; i += 4) {
        a0 = fmaf(w[i],     g_d1[(i)     * 32 + b], a0);
        a1 = fmaf(w[i + 1], g_d1[(i + 1) * 32 + b], a1);
        a2 = fmaf(w[i + 2], g_d1[(i + 2) * 32 + b], a2);
        a3 = fmaf(w[i + 3], g_d1[(i + 3) * 32 + b], a3);
    }
    g_d2[o * 32 + b] = fmaxf(bias[o] + ((a0 + a1) + (a2 + a3)), 0.f);
}

__global__ void dec3_kernel(const float* __restrict__ Wt,
                            const float* __restrict__ bias,
                            float* __restrict__ out) {
    int idx = blockIdx.x * 256 + threadIdx.x;   // 784*32
    int b = idx & 31, o = idx >> 5;
    const float* w = Wt + (size_t)o * 1024;
    float a0 = 0.f, a1 = 0.f, a2 = 0.f, a3 = 0.f;
#pragma unroll 4
    for (int i = 0; i < 1024; i += 4) {
        a0 = fmaf(w[i],     g_d2[(i)     * 32 + b], a0);
        a1 = fmaf(w[i + 1], g_d2[(i + 1) * 32 + b], a1);
        a2 = fmaf(w[i + 2], g_d2[(i + 2) * 32 + b], a2);
        a3 = fmaf(w[i + 3], g_d2[(i + 3) * 32 + b], a3);
    }
    float x = bias[o] + ((a0 + a1) + (a2 + a3));
    out[OFF_RECON + (size_t)b * 784 + o] = 1.f / (1.f + expf(-x));
}

// ---------------------------------------------------------------------------
// Resolve inputs by (unique) element count — order-independent binding.
// ---------------------------------------------------------------------------
static const float* by_size(void* const* d_in, const int* s, int n, int want) {
    for (int i = 0; i < n; ++i)
        if (s[i] == want) return (const float*)d_in[i];
    return nullptr;
}

extern "C" void kernel_launch(void* const* d_in, const int* in_sizes, int n_in,
                              void* d_out, int out_size) {
    const float* x   = by_size(d_in, in_sizes, n_in, 32 * 784);        // 25088
    const float* cw  = by_size(d_in, in_sizes, n_in, 256 * 81);        // 20736
    const float* cb  = by_size(d_in, in_sizes, n_in, 256);
    const float* fcw = by_size(d_in, in_sizes, n_in, 943718400);       // 9216*102400
    const float* fcb = by_size(d_in, in_sizes, n_in, 9216);
    const float* W   = by_size(d_in, in_sizes, n_in, 1474560);         // 10*1152*16*8
    const float* d1w = by_size(d_in, in_sizes, n_in, 512 * 160);       // 81920
    const float* d1b = by_size(d_in, in_sizes, n_in, 512);
    const float* d2w = by_size(d_in, in_sizes, n_in, 1024 * 512);      // 524288
    const float* d2b = by_size(d_in, in_sizes, n_in, 1024);
    const float* d3w = by_size(d_in, in_sizes, n_in, 784 * 1024);      // 802816
    const float* d3b = by_size(d_in, in_sizes, n_in, 784);
    float* out = (float*)d_out;

    xT_kernel<<<98, 256>>>(x);                           // launch 1
    conv_kernel<<<12800, 256>>>(cw, cb);                 // launch 2
    actcvt_kernel<<<12800, 256>>>();                     // launch 3
    fc_hmma_kernel<<<dim3(72, 8), 256>>>(fcw);           // launch 4 <- ncu slot
    caps_kernel<<<144, 256>>>(fcb, out);
    uhat_kernel<<<1440, 256>>>(W);

    // routing iteration 0 (c = softmax(0) = 0.1 uniform)
    rout_sv_kernel<<<360, 512>>>(1);
    rout_squash_kernel<<<1, 320>>>(0, out);
    rout_update_kernel<<<1440, 256>>>(1);
    // routing iteration 1
    softmax_kernel<<<144, 256>>>(0, out);
    rout_sv_kernel<<<360, 512>>>(0);
    rout_squash_kernel<<<1, 320>>>(0, out);
    rout_update_kernel<<<1440, 256>>>(0);
    // final pass (emit c, b, digit caps)
    softmax_kernel<<<144, 256>>>(1, out);
    rout_sv_kernel<<<360, 512>>>(0);
    rout_squash_kernel<<<1, 320>>>(1, out);

    logits_kernel<<<1, 32>>>(out);
    dec1_kernel<<<64, 256>>>(d1w, d1b);
    dec2_kernel<<<128, 256>>>(d2w, d2b);
    dec3_kernel<<<98, 256>>>(d3w, d3b, out);
}